// round 14
// baseline (speedup 1.0000x reference)
#include <cuda_runtime.h>
#include <cuda_bf16.h>
#include <stdint.h>

// ---------------------------------------------------------------------------
// Exact Chamfer via uniform-grid NN, v11: G=24 + float shell table + minimal
// shuffle traffic.
//   2 launches: [scatter + float-tab build + lastCTA count-pack] ->
//               [query + lastCTA reduce + re-zero].
//   G=24 (cell 1/3 over [-4,4]^3): densest cells ~38 pts. Shell table holds
//   {dx*cell, dy*cell, dz*cell, bits(dci)} grouped by Chebyshev r (closed
//   form rank, deterministic). Query (warp per query): per-lane cur always
//   (>= true min -> pruning/break conservative-exact); break via
//   ballot(lb^2 < cur); box-dist from clamped in-cell fraction fx (edge
//   extension for clamped outliers preserved as a valid lower bound);
//   survivor cells: one packed shfl, lane-strided scan; single final
//   butterfly. fp-min order-independent + fixed-order double reduce ->
//   deterministic output.
// ---------------------------------------------------------------------------

#define NPTS   16384
#define G      24
#define NC     (G*G*G)            // 13824 cells per array
#define CELLF  0.33333334f
#define GMINF  (-4.0f)
#define INVC   3.0f
#define CAP    96
#define NCTA_Q 4096
#define TABW   47                 // offsets -23..23
#define TABN   (TABW*TABW*TABW)   // 103823

__device__ int           g_n[2 * NC];     // zero at load; re-zeroed by query
__device__ unsigned char g_n8[2 * NC];    // byte counts (scatter lastCTA)
__device__ float4        g_bkt[2 * NC * CAP];
__device__ float         g_dmin[2 * NPTS];
__device__ float4        g_tab4[TABN];    // {dx*c, dy*c, dz*c, bits(dci)}
__device__ unsigned int  g_c1, g_c2;      // last-CTA counters (self-reset)

__device__ __forceinline__ int cell_of(float v) {
    int c = (int)floorf((v - GMINF) * INVC);
    return min(G - 1, max(0, c));
}
__device__ __forceinline__ int shell_base(int r) {   // (2r-1)^3, 0 @ r=0
    const int m = 2 * r - 1;
    return (r == 0) ? 0 : m * m * m;
}

// --------- scatter + float table build + lastCTA count pack ----------------
__global__ __launch_bounds__(1024)
void scatter_kernel(const float* __restrict__ pa, const float* __restrict__ pb) {
    const int t = blockIdx.x * 1024 + threadIdx.x;   // 32 CTAs -> 0..32767
    const int arr = t >> 14, i = t & (NPTS - 1);
    const float* s = arr ? pb : pa;
    const float x = s[3 * i + 0], y = s[3 * i + 1], z = s[3 * i + 2];
    const int ci = (cell_of(z) * G + cell_of(y)) * G + cell_of(x);
    const int pos = atomicAdd(&g_n[arr * NC + ci], 1);
    if (pos < CAP)
        g_bkt[(arr * NC + ci) * CAP + pos] = make_float4(x, y, z, 0.f);

    for (int e = t; e < TABN; e += 32768) {   // deterministic shell table
        const int dz = e / (TABW * TABW) - 23;
        const int rm = e % (TABW * TABW);
        const int dy = rm / TABW - 23;
        const int dx = rm % TABW - 23;
        const int r = max(abs(dx), max(abs(dy), abs(dz)));
        int rank = 0;
        if (r > 0) {
            const int w1 = 2 * r + 1, w0 = 2 * r - 1;
            if (abs(dz) == r) {                       // z-faces
                rank = ((dz == r) ? 0 : w1 * w1) + (dy + r) * w1 + (dx + r);
            } else if (abs(dy) == r) {                // y-faces
                rank = 2 * w1 * w1 + ((dy == r) ? 0 : w1 * w0)
                     + (dz + r - 1) * w1 + (dx + r);
            } else {                                  // x-faces
                rank = 2 * w1 * w1 + 2 * w1 * w0 + ((dx == r) ? 0 : w0 * w0)
                     + (dz + r - 1) * w0 + (dy + r - 1);
            }
        }
        const int dci = (dz * G + dy) * G + dx;
        g_tab4[shell_base(r) + rank] =
            make_float4(dx * CELLF, dy * CELLF, dz * CELLF,
                        __int_as_float(dci));
    }

    // ---- last CTA packs counts to bytes (fence->sync->vote->fence) ----
    __threadfence();
    __syncthreads();
    __shared__ unsigned s_last;
    if (threadIdx.x == 0) s_last = (atomicAdd(&g_c1, 1u) == 31u);
    __syncthreads();
    if (!s_last) return;
    __threadfence();
    if (threadIdx.x == 0) g_c1 = 0u;

    const int4* __restrict__ gn4 = (const int4*)g_n;
    uchar4* __restrict__ n84 = (uchar4*)g_n8;
    for (int k = threadIdx.x; k < 2 * NC / 4; k += 1024) {
        const int4 v = __ldcg(&gn4[k]);
        n84[k] = make_uchar4((unsigned char)min(v.x, CAP),
                             (unsigned char)min(v.y, CAP),
                             (unsigned char)min(v.z, CAP),
                             (unsigned char)min(v.w, CAP));
    }
}

// ---------------------- query + lastCTA reduce ------------------------------
__global__ __launch_bounds__(256)
void query_kernel(const float* __restrict__ pa, const float* __restrict__ pb,
                  float* __restrict__ out) {
    const unsigned full = 0xffffffffu;
    const int w    = blockIdx.x * 8 + (threadIdx.x >> 5);   // 0..32767
    const int lane = threadIdx.x & 31;
    const int arr  = w >> 14;
    const int i    = w & (NPTS - 1);
    const float* s = arr ? pb : pa;
    const float qx = s[3 * i + 0], qy = s[3 * i + 1], qz = s[3 * i + 2];
    const int cx = cell_of(qx), cy = cell_of(qy), cz = cell_of(qz);
    const unsigned char* __restrict__ cnts = &g_n8[(1 - arr) * NC];
    const float4* __restrict__ bkt = &g_bkt[(1 - arr) * NC * CAP];
    const int ci0 = (cz * G + cy) * G + cx;

    // clamped in-cell fractions (edge extension: clamp keeps bound valid)
    float fx = qx - fmaf((float)cx, CELLF, GMINF);
    float fy = qy - fmaf((float)cy, CELLF, GMINF);
    float fz = qz - fmaf((float)cz, CELLF, GMINF);
    fx = fminf(fmaxf(fx, 0.f), CELLF);
    fy = fminf(fmaxf(fy, 0.f), CELLF);
    fz = fminf(fmaxf(fz, 0.f), CELLF);
    // float bounds for offset validity (±half-cell margins: ulp-robust)
    const float lox = ((float)(-cx)     - 0.5f) * CELLF;
    const float hix = ((float)(G-1-cx)  + 0.5f) * CELLF;
    const float loy = ((float)(-cy)     - 0.5f) * CELLF;
    const float hiy = ((float)(G-1-cy)  + 0.5f) * CELLF;
    const float loz = ((float)(-cz)     - 0.5f) * CELLF;
    const float hiz = ((float)(G-1-cz)  + 0.5f) * CELLF;

    float cur = 3e38f;                    // per-lane everywhere

    // own cell first
    {
        const int cnt0 = __ldg(&cnts[ci0]);
        const float4* __restrict__ cp = &bkt[ci0 * CAP];
        for (int u = lane; u < cnt0; u += 32) {
            const float4 p = __ldg(&cp[u]);
            const float dx = qx - p.x, dy = qy - p.y, dz = qz - p.z;
            cur = fminf(cur, fmaf(dx, dx, fmaf(dy, dy, dz * dz)));
        }
    }

    for (int r = 1; r < G; ++r) {
        const float lb = (float)(r - 1) * (CELLF * 0.999f);
        if (!__ballot_sync(full, lb * lb < cur)) break;
        const int base = shell_base(r);
        const int size = shell_base(r + 1) - base;

        for (int pass = 0; pass < size; pass += 32) {
            const int idx = pass + lane;
            int pk = 0;
            float bd2 = 3e38f;
            if (idx < size) {
                const float4 e = __ldg(&g_tab4[base + idx]);
                if ((e.x > lox) & (e.x < hix) & (e.y > loy) & (e.y < hiy) &
                    (e.z > loz) & (e.z < hiz)) {
                    const int ci = ci0 + __float_as_int(e.w);
                    const int cnt = __ldg(&cnts[ci]);
                    if (cnt > 0) {
                        const float bx =
                            fmaxf(fmaxf(e.x - fx, fx - e.x - CELLF), 0.f);
                        const float by =
                            fmaxf(fmaxf(e.y - fy, fy - e.y - CELLF), 0.f);
                        const float bz =
                            fmaxf(fmaxf(e.z - fz, fz - e.z - CELLF), 0.f);
                        bd2 = fmaf(bx, bx, fmaf(by, by, bz * bz));
                        pk = (ci << 8) | cnt;
                    }
                }
            }
            unsigned mask = __ballot_sync(full, bd2 < cur);  // per-lane: safe
            while (mask) {
                const int src = __ffs(mask) - 1;
                mask &= mask - 1;
                const int pks = __shfl_sync(full, pk, src);  // one shfl/cell
                const int cnt_s = pks & 255;
                const float4* __restrict__ cp = &bkt[(pks >> 8) * CAP];
                for (int u = lane; u < cnt_s; u += 32) {
                    const float4 p = __ldg(&cp[u]);
                    const float dx = qx - p.x, dy = qy - p.y, dz = qz - p.z;
                    cur = fminf(cur, fmaf(dx, dx, fmaf(dy, dy, dz * dz)));
                }
            }
        }
    }
    // single final butterfly
    #pragma unroll
    for (int o = 16; o; o >>= 1)
        cur = fminf(cur, __shfl_xor_sync(full, cur, o));
    if (lane == 0) g_dmin[w] = cur;

    // ---- last-CTA fixed-order reduce (fence -> sync -> vote -> fence) ----
    __threadfence();
    __syncthreads();
    __shared__ unsigned s_last;
    if (threadIdx.x == 0) s_last = (atomicAdd(&g_c2, 1u) == NCTA_Q - 1u);
    __syncthreads();
    if (!s_last) return;
    __threadfence();
    if (threadIdx.x == 0) g_c2 = 0u;

    __shared__ double sm[256];
    const int tid = threadIdx.x;
    double acc = 0.0;
    for (int k = tid; k < 2 * NPTS; k += 256)
        acc += (double)__ldcg(&g_dmin[k]);
    sm[tid] = acc;
    __syncthreads();
    for (int o = 128; o; o >>= 1) {
        if (tid < o) sm[tid] += sm[tid + o];
        __syncthreads();
    }
    if (tid == 0) out[0] = (float)(sm[0] * (1.0 / (double)NPTS));

    // re-zero bucket counts for next graph replay
    int4* gn4 = (int4*)g_n;
    const int4 z4 = make_int4(0, 0, 0, 0);
    for (int k = tid; k < 2 * NC / 4; k += 256) gn4[k] = z4;
}

extern "C" void kernel_launch(void* const* d_in, const int* in_sizes, int n_in,
                              void* d_out, int out_size) {
    const float* p_hat = (const float*)d_in[0];  // [16384,3]
    const float* p     = (const float*)d_in[1];  // [16384,3]
    float* out = (float*)d_out;

    scatter_kernel<<<32, 1024>>>(p_hat, p);
    query_kernel<<<NCTA_Q, 256>>>(p_hat, p, out);
}

// round 15
// speedup vs baseline: 21.1177x; 21.1177x over previous
#include <cuda_runtime.h>
#include <cuda_bf16.h>
#include <stdint.h>

// ---------------------------------------------------------------------------
// Exact Chamfer via uniform-grid NN, v12 = v11 + restored per-shell butterfly
// (v11's per-lane break never fired: lanes with index >= all cell counts kept
// cur = +inf forever -> full-table walks -> 1.6 ms. Butterfly at each shell
// boundary makes cur warp-uniform so the break is sound and early.)
//   G=24 (cell 1/3), float shell table {dx*c,dy*c,dz*c,bits(dci)} (no I2F on
//   the walk), own-cell-first, byte counts, one shfl per survivor cell.
//   Exactness: box-dist pruning with clamped in-cell fractions (edge
//   extension preserved -> clamped outliers exact); per-lane cur >= true min
//   within a shell -> pruning conservative; shell break on warp-uniform cur.
//   fp-min order-independent + fixed-order double reduce -> deterministic.
// ---------------------------------------------------------------------------

#define NPTS   16384
#define G      24
#define NC     (G*G*G)            // 13824 cells per array
#define CELLF  0.33333334f
#define GMINF  (-4.0f)
#define INVC   3.0f
#define CAP    96
#define NCTA_Q 4096
#define TABW   47                 // offsets -23..23
#define TABN   (TABW*TABW*TABW)   // 103823

__device__ int           g_n[2 * NC];     // zero at load; re-zeroed by query
__device__ unsigned char g_n8[2 * NC];    // byte counts (scatter lastCTA)
__device__ float4        g_bkt[2 * NC * CAP];
__device__ float         g_dmin[2 * NPTS];
__device__ float4        g_tab4[TABN];    // {dx*c, dy*c, dz*c, bits(dci)}
__device__ unsigned int  g_c1, g_c2;      // last-CTA counters (self-reset)

__device__ __forceinline__ int cell_of(float v) {
    int c = (int)floorf((v - GMINF) * INVC);
    return min(G - 1, max(0, c));
}
__device__ __forceinline__ int shell_base(int r) {   // (2r-1)^3, 0 @ r=0
    const int m = 2 * r - 1;
    return (r == 0) ? 0 : m * m * m;
}

// --------- scatter + float table build + lastCTA count pack ----------------
__global__ __launch_bounds__(1024)
void scatter_kernel(const float* __restrict__ pa, const float* __restrict__ pb) {
    const int t = blockIdx.x * 1024 + threadIdx.x;   // 32 CTAs -> 0..32767
    const int arr = t >> 14, i = t & (NPTS - 1);
    const float* s = arr ? pb : pa;
    const float x = s[3 * i + 0], y = s[3 * i + 1], z = s[3 * i + 2];
    const int ci = (cell_of(z) * G + cell_of(y)) * G + cell_of(x);
    const int pos = atomicAdd(&g_n[arr * NC + ci], 1);
    if (pos < CAP)
        g_bkt[(arr * NC + ci) * CAP + pos] = make_float4(x, y, z, 0.f);

    for (int e = t; e < TABN; e += 32768) {   // deterministic shell table
        const int dz = e / (TABW * TABW) - 23;
        const int rm = e % (TABW * TABW);
        const int dy = rm / TABW - 23;
        const int dx = rm % TABW - 23;
        const int r = max(abs(dx), max(abs(dy), abs(dz)));
        int rank = 0;
        if (r > 0) {
            const int w1 = 2 * r + 1, w0 = 2 * r - 1;
            if (abs(dz) == r) {                       // z-faces
                rank = ((dz == r) ? 0 : w1 * w1) + (dy + r) * w1 + (dx + r);
            } else if (abs(dy) == r) {                // y-faces
                rank = 2 * w1 * w1 + ((dy == r) ? 0 : w1 * w0)
                     + (dz + r - 1) * w1 + (dx + r);
            } else {                                  // x-faces
                rank = 2 * w1 * w1 + 2 * w1 * w0 + ((dx == r) ? 0 : w0 * w0)
                     + (dz + r - 1) * w0 + (dy + r - 1);
            }
        }
        const int dci = (dz * G + dy) * G + dx;
        g_tab4[shell_base(r) + rank] =
            make_float4(dx * CELLF, dy * CELLF, dz * CELLF,
                        __int_as_float(dci));
    }

    // ---- last CTA packs counts to bytes (fence->sync->vote->fence) ----
    __threadfence();
    __syncthreads();
    __shared__ unsigned s_last;
    if (threadIdx.x == 0) s_last = (atomicAdd(&g_c1, 1u) == 31u);
    __syncthreads();
    if (!s_last) return;
    __threadfence();
    if (threadIdx.x == 0) g_c1 = 0u;

    const int4* __restrict__ gn4 = (const int4*)g_n;
    uchar4* __restrict__ n84 = (uchar4*)g_n8;
    for (int k = threadIdx.x; k < 2 * NC / 4; k += 1024) {
        const int4 v = __ldcg(&gn4[k]);
        n84[k] = make_uchar4((unsigned char)min(v.x, CAP),
                             (unsigned char)min(v.y, CAP),
                             (unsigned char)min(v.z, CAP),
                             (unsigned char)min(v.w, CAP));
    }
}

// ---------------------- query + lastCTA reduce ------------------------------
__global__ __launch_bounds__(256)
void query_kernel(const float* __restrict__ pa, const float* __restrict__ pb,
                  float* __restrict__ out) {
    const unsigned full = 0xffffffffu;
    const int w    = blockIdx.x * 8 + (threadIdx.x >> 5);   // 0..32767
    const int lane = threadIdx.x & 31;
    const int arr  = w >> 14;
    const int i    = w & (NPTS - 1);
    const float* s = arr ? pb : pa;
    const float qx = s[3 * i + 0], qy = s[3 * i + 1], qz = s[3 * i + 2];
    const int cx = cell_of(qx), cy = cell_of(qy), cz = cell_of(qz);
    const unsigned char* __restrict__ cnts = &g_n8[(1 - arr) * NC];
    const float4* __restrict__ bkt = &g_bkt[(1 - arr) * NC * CAP];
    const int ci0 = (cz * G + cy) * G + cx;

    // clamped in-cell fractions (edge extension: clamp keeps bound valid)
    float fx = qx - fmaf((float)cx, CELLF, GMINF);
    float fy = qy - fmaf((float)cy, CELLF, GMINF);
    float fz = qz - fmaf((float)cz, CELLF, GMINF);
    fx = fminf(fmaxf(fx, 0.f), CELLF);
    fy = fminf(fmaxf(fy, 0.f), CELLF);
    fz = fminf(fmaxf(fz, 0.f), CELLF);
    // float bounds for offset validity (±half-cell margins: ulp-robust)
    const float lox = ((float)(-cx)     - 0.5f) * CELLF;
    const float hix = ((float)(G-1-cx)  + 0.5f) * CELLF;
    const float loy = ((float)(-cy)     - 0.5f) * CELLF;
    const float hiy = ((float)(G-1-cy)  + 0.5f) * CELLF;
    const float loz = ((float)(-cz)     - 0.5f) * CELLF;
    const float hiz = ((float)(G-1-cz)  + 0.5f) * CELLF;

    float cur = 3e38f;    // per-lane inside shells; warp-uniform at boundary

    // own cell first
    {
        const int cnt0 = __ldg(&cnts[ci0]);
        const float4* __restrict__ cp = &bkt[ci0 * CAP];
        for (int u = lane; u < cnt0; u += 32) {
            const float4 p = __ldg(&cp[u]);
            const float dx = qx - p.x, dy = qy - p.y, dz = qz - p.z;
            cur = fminf(cur, fmaf(dx, dx, fmaf(dy, dy, dz * dz)));
        }
        #pragma unroll
        for (int o = 16; o; o >>= 1)
            cur = fminf(cur, __shfl_xor_sync(full, cur, o));
    }

    for (int r = 1; r < G; ++r) {
        const float lb = (float)(r - 1) * (CELLF * 0.999f);
        if (lb * lb >= cur) break;        // cur warp-uniform here
        const int base = shell_base(r);
        const int size = shell_base(r + 1) - base;

        for (int pass = 0; pass < size; pass += 32) {
            const int idx = pass + lane;
            int pk = 0;
            float bd2 = 3e38f;
            if (idx < size) {
                const float4 e = __ldg(&g_tab4[base + idx]);
                if ((e.x > lox) & (e.x < hix) & (e.y > loy) & (e.y < hiy) &
                    (e.z > loz) & (e.z < hiz)) {
                    const int ci = ci0 + __float_as_int(e.w);
                    const int cnt = __ldg(&cnts[ci]);
                    if (cnt > 0) {
                        const float bx =
                            fmaxf(fmaxf(e.x - fx, fx - e.x - CELLF), 0.f);
                        const float by =
                            fmaxf(fmaxf(e.y - fy, fy - e.y - CELLF), 0.f);
                        const float bz =
                            fmaxf(fmaxf(e.z - fz, fz - e.z - CELLF), 0.f);
                        bd2 = fmaf(bx, bx, fmaf(by, by, bz * bz));
                        pk = (ci << 8) | cnt;
                    }
                }
            }
            unsigned mask = __ballot_sync(full, bd2 < cur);  // per-lane: safe
            while (mask) {
                const int src = __ffs(mask) - 1;
                mask &= mask - 1;
                const int pks = __shfl_sync(full, pk, src);  // one shfl/cell
                const int cnt_s = pks & 255;
                const float4* __restrict__ cp = &bkt[(pks >> 8) * CAP];
                for (int u = lane; u < cnt_s; u += 32) {
                    const float4 p = __ldg(&cp[u]);
                    const float dx = qx - p.x, dy = qy - p.y, dz = qz - p.z;
                    cur = fminf(cur, fmaf(dx, dx, fmaf(dy, dy, dz * dz)));
                }
            }
        }
        // shell boundary: restore warp-uniform cur (THE v14 FIX)
        #pragma unroll
        for (int o = 16; o; o >>= 1)
            cur = fminf(cur, __shfl_xor_sync(full, cur, o));
    }
    if (lane == 0) g_dmin[w] = cur;

    // ---- last-CTA fixed-order reduce (fence -> sync -> vote -> fence) ----
    __threadfence();
    __syncthreads();
    __shared__ unsigned s_last;
    if (threadIdx.x == 0) s_last = (atomicAdd(&g_c2, 1u) == NCTA_Q - 1u);
    __syncthreads();
    if (!s_last) return;
    __threadfence();
    if (threadIdx.x == 0) g_c2 = 0u;

    __shared__ double sm[256];
    const int tid = threadIdx.x;
    double acc = 0.0;
    for (int k = tid; k < 2 * NPTS; k += 256)
        acc += (double)__ldcg(&g_dmin[k]);
    sm[tid] = acc;
    __syncthreads();
    for (int o = 128; o; o >>= 1) {
        if (tid < o) sm[tid] += sm[tid + o];
        __syncthreads();
    }
    if (tid == 0) out[0] = (float)(sm[0] * (1.0 / (double)NPTS));

    // re-zero bucket counts for next graph replay
    int4* gn4 = (int4*)g_n;
    const int4 z4 = make_int4(0, 0, 0, 0);
    for (int k = tid; k < 2 * NC / 4; k += 256) gn4[k] = z4;
}

extern "C" void kernel_launch(void* const* d_in, const int* in_sizes, int n_in,
                              void* d_out, int out_size) {
    const float* p_hat = (const float*)d_in[0];  // [16384,3]
    const float* p     = (const float*)d_in[1];  // [16384,3]
    float* out = (float*)d_out;

    scatter_kernel<<<32, 1024>>>(p_hat, p);
    query_kernel<<<NCTA_Q, 256>>>(p_hat, p, out);
}

// round 16
// speedup vs baseline: 21.7038x; 1.0278x over previous
#include <cuda_runtime.h>
#include <cuda_bf16.h>
#include <stdint.h>

// ---------------------------------------------------------------------------
// Exact Chamfer via uniform-grid NN, v13 = v10 query engine (G=16, measured
// best) + CELL-SORTED compact storage so adjacent warps share L1 for counts,
// shell table, and candidate lines.
//   4 launches: hist -> prefix (2 CTAs, one per array; re-zeros g_n) ->
//   scatter (compact counting-sort + closed-form shell table) ->
//   query + lastCTA reduce.
//   Query (warp per query, queries taken in cell-sorted order from g_pts):
//   shells enumerated 32 offsets/pass (bounds, cnt>0, exact box-dist <
//   per-lane cur; edge cells extend to infinity -> clamped outliers exact);
//   survivor cells scanned lane-strided (x2 unroll); per-shell butterfly
//   restores warp-uniform cur for the sound break ((r-1)*cell)^2 >= cur.
//   fp-min order-independent + fixed-order double reduce -> deterministic.
// ---------------------------------------------------------------------------

#define NPTS   16384
#define G      16
#define NC     (G*G*G)          // 4096 cells per array
#define CELLF  0.5f
#define GMINF  (-4.0f)
#define INVC   2.0f
#define NCTA_Q 4096
#define TABN   29791            // 31^3 offsets (r <= 15)

__device__ int          g_n[2 * NC];     // zero at load; re-zeroed by prefix
__device__ int          g_cur[2 * NC];
__device__ int2         g_meta[2 * NC];  // (flat offset into g_pts, count)
__device__ float4       g_pts[2 * NPTS]; // cell-sorted; w = global slot bits
__device__ float        g_dmin[2 * NPTS];
__device__ int          g_tab[TABN];     // (dx+15)|(dy+15)<<5|(dz+15)<<10
__device__ unsigned int g_c2;            // last-CTA counter (self-reset)

__device__ __forceinline__ int cell_of(float v) {
    int c = (int)floorf((v - GMINF) * INVC);
    return min(G - 1, max(0, c));
}
__device__ __forceinline__ float axis_bd(float q, int X) {
    const float lo = GMINF + X * CELLF, hi = lo + CELLF;
    float b = 0.f;
    if (q < lo)      { if (X > 0)     b = lo - q; }
    else if (q > hi) { if (X < G - 1) b = q - hi; }
    return b;
}
__device__ __forceinline__ int shell_base(int r) {   // (2r-1)^3, 0 @ r=0
    const int m = 2 * r - 1;
    return (r == 0) ? 0 : m * m * m;
}

// --------------------------------- hist ------------------------------------
__global__ __launch_bounds__(1024)
void hist_kernel(const float* __restrict__ pa, const float* __restrict__ pb) {
    const int t = blockIdx.x * 1024 + threadIdx.x;   // 32 CTAs -> 0..32767
    const int arr = t >> 14, i = t & (NPTS - 1);
    const float* s = arr ? pb : pa;
    const int ci = (cell_of(s[3 * i + 2]) * G + cell_of(s[3 * i + 1])) * G
                   + cell_of(s[3 * i + 0]);
    atomicAdd(&g_n[arr * NC + ci], 1);
}

// ------------------- prefix: one CTA per array (independent) ---------------
__global__ __launch_bounds__(1024)
void prefix_kernel() {
    __shared__ int sc[1024];
    const int arr = blockIdx.x, tid = threadIdx.x;
    int4* __restrict__ gn4 = (int4*)&g_n[arr * NC];
    const int4 v = __ldcg(&gn4[tid]);                // 4 cells/thread
    const int tot = v.x + v.y + v.z + v.w;
    sc[tid] = tot;
    __syncthreads();
    for (int off = 1; off < 1024; off <<= 1) {       // Hillis-Steele inclusive
        int s = sc[tid];
        int add = (tid >= off) ? sc[tid - off] : 0;
        __syncthreads();
        sc[tid] = s + add;
        __syncthreads();
    }
    int run = arr * NPTS + sc[tid] - tot;            // arr1 base = 16384
    const int base = arr * NC + tid * 4;
    const int c[4] = {v.x, v.y, v.z, v.w};
    #pragma unroll
    for (int k = 0; k < 4; ++k) {
        g_meta[base + k] = make_int2(run, c[k]);
        g_cur[base + k]  = run;
        run += c[k];
    }
    gn4[tid] = make_int4(0, 0, 0, 0);                // re-zero for replay
}

// --------------- scatter (compact) + closed-form shell table ---------------
__global__ __launch_bounds__(1024)
void scatter_kernel(const float* __restrict__ pa, const float* __restrict__ pb) {
    const int t = blockIdx.x * 1024 + threadIdx.x;   // 32 CTAs -> 0..32767
    const int arr = t >> 14, i = t & (NPTS - 1);
    const float* s = arr ? pb : pa;
    const float x = s[3 * i + 0], y = s[3 * i + 1], z = s[3 * i + 2];
    const int ci = (cell_of(z) * G + cell_of(y)) * G + cell_of(x);
    const int pos = atomicAdd(&g_cur[arr * NC + ci], 1);
    g_pts[pos] = make_float4(x, y, z, __int_as_float(arr * NPTS + i));

    if (t < TABN) {   // deterministic closed-form rank within shell r
        const int dz = t / 961 - 15;
        const int rm = t % 961;
        const int dy = rm / 31 - 15;
        const int dx = rm % 31 - 15;
        const int r = max(abs(dx), max(abs(dy), abs(dz)));
        int rank = 0;
        if (r > 0) {
            const int w1 = 2 * r + 1, w0 = 2 * r - 1;
            if (abs(dz) == r) {                       // z-faces
                rank = ((dz == r) ? 0 : w1 * w1) + (dy + r) * w1 + (dx + r);
            } else if (abs(dy) == r) {                // y-faces
                rank = 2 * w1 * w1 + ((dy == r) ? 0 : w1 * w0)
                     + (dz + r - 1) * w1 + (dx + r);
            } else {                                  // x-faces
                rank = 2 * w1 * w1 + 2 * w1 * w0 + ((dx == r) ? 0 : w0 * w0)
                     + (dz + r - 1) * w0 + (dy + r - 1);
            }
        }
        g_tab[shell_base(r) + rank] =
            (dx + 15) | ((dy + 15) << 5) | ((dz + 15) << 10);
    }
}

// ---------------------- query + lastCTA reduce ------------------------------
__global__ __launch_bounds__(256)
void query_kernel(float* __restrict__ out) {
    const unsigned full = 0xffffffffu;
    const int w    = blockIdx.x * 8 + (threadIdx.x >> 5);   // 0..32767, sorted
    const int lane = threadIdx.x & 31;
    const int arr  = w >> 14;                 // arr0 = slots 0..16383
    const float4 q = __ldg(&g_pts[w]);        // broadcast load
    const float qx = q.x, qy = q.y, qz = q.z;
    const int cx = cell_of(qx), cy = cell_of(qy), cz = cell_of(qz);
    const int2* __restrict__ meta = &g_meta[(1 - arr) * NC];

    float cur = 3e38f;    // per-lane inside shells; warp-uniform at boundary

    for (int r = 0; r < 16; ++r) {
        if (r >= 1) {
            const float lb = (float)(r - 1) * CELLF;
            if (lb * lb >= cur) break;        // cur warp-uniform here
        }
        const int base = shell_base(r);
        const int size = shell_base(r + 1) - base;

        for (int pass = 0; pass < size; pass += 32) {
            const int idx = pass + lane;
            int off = 0, cnt = 0;
            float bd2 = 3e38f;
            if (idx < size) {
                const int e = __ldg(&g_tab[base + idx]);
                const int X = cx + (e & 31) - 15;
                const int Y = cy + ((e >> 5) & 31) - 15;
                const int Z = cz + ((e >> 10) & 31) - 15;
                if (((unsigned)X < G) & ((unsigned)Y < G) & ((unsigned)Z < G)) {
                    const int2 mc = __ldg(&meta[(Z * G + Y) * G + X]);
                    if (mc.y > 0) {
                        const float bx = axis_bd(qx, X);
                        const float by = axis_bd(qy, Y);
                        const float bz = axis_bd(qz, Z);
                        bd2 = fmaf(bx, bx, fmaf(by, by, bz * bz));
                        off = mc.x; cnt = mc.y;
                    }
                }
            }
            unsigned mask = __ballot_sync(full, bd2 < cur);  // per-lane: safe
            while (mask) {
                const int src = __ffs(mask) - 1;
                mask &= mask - 1;
                const int off_s = __shfl_sync(full, off, src);
                const int cnt_s = __shfl_sync(full, cnt, src);
                const float4* __restrict__ cp = &g_pts[off_s];
                int u = lane;
                for (; u + 32 < cnt_s; u += 64) {      // 2 loads in flight
                    const float4 p0 = __ldg(&cp[u]);
                    const float4 p1 = __ldg(&cp[u + 32]);
                    const float dx0 = qx - p0.x, dy0 = qy - p0.y, dz0 = qz - p0.z;
                    const float dx1 = qx - p1.x, dy1 = qy - p1.y, dz1 = qz - p1.z;
                    cur = fminf(cur, fmaf(dx0, dx0, fmaf(dy0, dy0, dz0 * dz0)));
                    cur = fminf(cur, fmaf(dx1, dx1, fmaf(dy1, dy1, dz1 * dz1)));
                }
                if (u < cnt_s) {
                    const float4 p0 = __ldg(&cp[u]);
                    const float dx0 = qx - p0.x, dy0 = qy - p0.y, dz0 = qz - p0.z;
                    cur = fminf(cur, fmaf(dx0, dx0, fmaf(dy0, dy0, dz0 * dz0)));
                }
            }
        }
        // shell boundary: restore warp-uniform cur
        #pragma unroll
        for (int o = 16; o; o >>= 1)
            cur = fminf(cur, __shfl_xor_sync(full, cur, o));
    }
    if (lane == 0) g_dmin[__float_as_int(q.w)] = cur;

    // ---- last-CTA fixed-order reduce (fence -> sync -> vote -> fence) ----
    __threadfence();
    __syncthreads();
    __shared__ unsigned s_last;
    if (threadIdx.x == 0) s_last = (atomicAdd(&g_c2, 1u) == NCTA_Q - 1u);
    __syncthreads();
    if (!s_last) return;
    __threadfence();
    if (threadIdx.x == 0) g_c2 = 0u;

    __shared__ double sm[256];
    const int tid = threadIdx.x;
    double acc = 0.0;
    for (int k = tid; k < 2 * NPTS; k += 256)
        acc += (double)__ldcg(&g_dmin[k]);
    sm[tid] = acc;
    __syncthreads();
    for (int o = 128; o; o >>= 1) {
        if (tid < o) sm[tid] += sm[tid + o];
        __syncthreads();
    }
    if (tid == 0) out[0] = (float)(sm[0] * (1.0 / (double)NPTS));
}

extern "C" void kernel_launch(void* const* d_in, const int* in_sizes, int n_in,
                              void* d_out, int out_size) {
    const float* p_hat = (const float*)d_in[0];  // [16384,3]
    const float* p     = (const float*)d_in[1];  // [16384,3]
    float* out = (float*)d_out;

    hist_kernel<<<32, 1024>>>(p_hat, p);
    prefix_kernel<<<2, 1024>>>();
    scatter_kernel<<<32, 1024>>>(p_hat, p);
    query_kernel<<<NCTA_Q, 256>>>(out);
}

// round 17
// speedup vs baseline: 26.6644x; 1.2286x over previous
#include <cuda_runtime.h>
#include <cuda_bf16.h>
#include <stdint.h>

// ---------------------------------------------------------------------------
// Exact Chamfer via uniform-grid NN, v14 = v10 (measured best: G=16, bucket
// grid, byte counts, unsorted queries, per-lane cur inside shells + per-shell
// butterfly) + ONE change: the opposite array's 4 KB byte-count table is
// staged into SMEM per CTA, converting the scattered ~250-cycle L2 count
// load on every enumeration pass's critical chain into a 29-cycle LDS.
//   2 launches: [scatter + analytic shell table + lastCTA count-pack] ->
//               [query + lastCTA reduce + g_n re-zero].
//   Exactness: exact box-distance pruning (edge cells extend to infinity ->
//   clamped outliers exact); per-lane cur >= true min within a shell ->
//   pruning conservative; shell break on warp-uniform cur after butterfly.
//   fp-min order-independent + fixed-order double reduce -> deterministic.
// ---------------------------------------------------------------------------

#define NPTS   16384
#define G      16
#define NC     (G*G*G)          // 4096 cells per array
#define CELLF  0.5f
#define GMINF  (-4.0f)
#define INVC   2.0f
#define CAP    192
#define NCTA_Q 4096
#define TABN   29791            // 31^3 offsets (r <= 15)

__device__ int           g_n[2 * NC];     // zero at load; re-zeroed by query
__device__ unsigned char g_n8[2 * NC];    // byte counts (scatter lastCTA)
__device__ float4        g_bkt[2 * NC * CAP];
__device__ float         g_dmin[2 * NPTS];
__device__ int           g_tab[TABN];     // (dx+15)|(dy+15)<<5|(dz+15)<<10
__device__ unsigned int  g_c1, g_c2;      // last-CTA counters (self-reset)

__device__ __forceinline__ int cell_of(float v) {
    int c = (int)floorf((v - GMINF) * INVC);
    return min(G - 1, max(0, c));
}
__device__ __forceinline__ float axis_bd(float q, int X) {
    const float lo = GMINF + X * CELLF, hi = lo + CELLF;
    float b = 0.f;
    if (q < lo)      { if (X > 0)     b = lo - q; }
    else if (q > hi) { if (X < G - 1) b = q - hi; }
    return b;
}
__device__ __forceinline__ int shell_base(int r) {   // (2r-1)^3, 0 @ r=0
    const int m = 2 * r - 1;
    return (r == 0) ? 0 : m * m * m;
}

// --------- scatter + analytic table build + lastCTA count pack -------------
__global__ __launch_bounds__(1024)
void scatter_kernel(const float* __restrict__ pa, const float* __restrict__ pb) {
    const int t = blockIdx.x * 1024 + threadIdx.x;   // 32 CTAs -> 0..32767
    const int arr = t >> 14, i = t & (NPTS - 1);
    const float* s = arr ? pb : pa;
    const float x = s[3 * i + 0], y = s[3 * i + 1], z = s[3 * i + 2];
    const int ci = (cell_of(z) * G + cell_of(y)) * G + cell_of(x);
    const int pos = atomicAdd(&g_n[arr * NC + ci], 1);
    if (pos < CAP)
        g_bkt[(arr * NC + ci) * CAP + pos] = make_float4(x, y, z, 0.f);

    if (t < TABN) {   // deterministic closed-form rank within shell r
        const int dz = t / 961 - 15;
        const int rm = t % 961;
        const int dy = rm / 31 - 15;
        const int dx = rm % 31 - 15;
        const int r = max(abs(dx), max(abs(dy), abs(dz)));
        int rank = 0;
        if (r > 0) {
            const int w1 = 2 * r + 1, w0 = 2 * r - 1;
            if (abs(dz) == r) {                       // z-faces
                rank = ((dz == r) ? 0 : w1 * w1) + (dy + r) * w1 + (dx + r);
            } else if (abs(dy) == r) {                // y-faces
                rank = 2 * w1 * w1 + ((dy == r) ? 0 : w1 * w0)
                     + (dz + r - 1) * w1 + (dx + r);
            } else {                                  // x-faces
                rank = 2 * w1 * w1 + 2 * w1 * w0 + ((dx == r) ? 0 : w0 * w0)
                     + (dz + r - 1) * w0 + (dy + r - 1);
            }
        }
        g_tab[shell_base(r) + rank] =
            (dx + 15) | ((dy + 15) << 5) | ((dz + 15) << 10);
    }

    // ---- last CTA packs counts to bytes (fence->sync->vote->fence) ----
    __threadfence();
    __syncthreads();
    __shared__ unsigned s_last;
    if (threadIdx.x == 0) s_last = (atomicAdd(&g_c1, 1u) == 31u);
    __syncthreads();
    if (!s_last) return;
    __threadfence();
    if (threadIdx.x == 0) g_c1 = 0u;

    const int4* __restrict__ gn4 = (const int4*)g_n;
    uchar4* __restrict__ n84 = (uchar4*)g_n8;
    for (int k = threadIdx.x; k < 2 * NC / 4; k += 1024) {
        const int4 v = __ldcg(&gn4[k]);
        n84[k] = make_uchar4((unsigned char)min(v.x, CAP),
                             (unsigned char)min(v.y, CAP),
                             (unsigned char)min(v.z, CAP),
                             (unsigned char)min(v.w, CAP));
    }
}

// ---------------------- query + lastCTA reduce ------------------------------
__global__ __launch_bounds__(256)
void query_kernel(const float* __restrict__ pa, const float* __restrict__ pb,
                  float* __restrict__ out) {
    __shared__ unsigned char s_cnt[NC];   // opposite array's counts (4 KB)
    const unsigned full = 0xffffffffu;
    const int w    = blockIdx.x * 8 + (threadIdx.x >> 5);   // 0..32767
    const int lane = threadIdx.x & 31;
    const int arr  = w >> 14;                               // CTA-uniform
    const int i    = w & (NPTS - 1);

    {   // stage counts: exactly one int4 per thread
        const int4* __restrict__ gc = (const int4*)&g_n8[(1 - arr) * NC];
        ((int4*)s_cnt)[threadIdx.x] = __ldg(&gc[threadIdx.x]);
    }
    __syncthreads();

    const float* s = arr ? pb : pa;
    const float qx = s[3 * i + 0], qy = s[3 * i + 1], qz = s[3 * i + 2];
    const int cx = cell_of(qx), cy = cell_of(qy), cz = cell_of(qz);
    const float4* __restrict__ bkt = &g_bkt[(1 - arr) * NC * CAP];

    float cur = 3e38f;    // per-lane inside shells; warp-uniform at boundary

    for (int r = 0; r < 16; ++r) {
        if (r >= 1) {
            const float lb = (float)(r - 1) * CELLF;
            if (lb * lb >= cur) break;    // cur warp-uniform here
        }
        const int base = shell_base(r);
        const int size = shell_base(r + 1) - base;

        for (int pass = 0; pass < size; pass += 32) {
            const int idx = pass + lane;
            int ci = 0, cnt = 0;
            float bd2 = 3e38f;
            if (idx < size) {
                const int e = __ldg(&g_tab[base + idx]);
                const int X = cx + (e & 31) - 15;
                const int Y = cy + ((e >> 5) & 31) - 15;
                const int Z = cz + ((e >> 10) & 31) - 15;
                if (((unsigned)X < G) & ((unsigned)Y < G) & ((unsigned)Z < G)) {
                    ci = (Z * G + Y) * G + X;
                    cnt = s_cnt[ci];                 // LDS, not L2
                    if (cnt > 0) {
                        const float bx = axis_bd(qx, X);
                        const float by = axis_bd(qy, Y);
                        const float bz = axis_bd(qz, Z);
                        bd2 = fmaf(bx, bx, fmaf(by, by, bz * bz));
                    }
                }
            }
            unsigned mask = __ballot_sync(full, bd2 < cur);  // per-lane: safe
            while (mask) {
                const int src = __ffs(mask) - 1;
                mask &= mask - 1;
                const int ci_s  = __shfl_sync(full, ci, src);
                const int cnt_s = __shfl_sync(full, cnt, src);
                const float4* __restrict__ cp = &bkt[ci_s * CAP];
                int u = lane;
                for (; u + 32 < cnt_s; u += 64) {      // 2 loads in flight
                    const float4 p0 = __ldg(&cp[u]);
                    const float4 p1 = __ldg(&cp[u + 32]);
                    const float dx0 = qx - p0.x, dy0 = qy - p0.y, dz0 = qz - p0.z;
                    const float dx1 = qx - p1.x, dy1 = qy - p1.y, dz1 = qz - p1.z;
                    cur = fminf(cur, fmaf(dx0, dx0, fmaf(dy0, dy0, dz0 * dz0)));
                    cur = fminf(cur, fmaf(dx1, dx1, fmaf(dy1, dy1, dz1 * dz1)));
                }
                if (u < cnt_s) {
                    const float4 p0 = __ldg(&cp[u]);
                    const float dx0 = qx - p0.x, dy0 = qy - p0.y, dz0 = qz - p0.z;
                    cur = fminf(cur, fmaf(dx0, dx0, fmaf(dy0, dy0, dz0 * dz0)));
                }
            }
        }
        // shell boundary: restore warp-uniform cur
        #pragma unroll
        for (int o = 16; o; o >>= 1)
            cur = fminf(cur, __shfl_xor_sync(full, cur, o));
    }
    if (lane == 0) g_dmin[w] = cur;

    // ---- last-CTA fixed-order reduce (fence -> sync -> vote -> fence) ----
    __threadfence();
    __syncthreads();
    __shared__ unsigned s_last;
    if (threadIdx.x == 0) s_last = (atomicAdd(&g_c2, 1u) == NCTA_Q - 1u);
    __syncthreads();
    if (!s_last) return;
    __threadfence();
    if (threadIdx.x == 0) g_c2 = 0u;

    __shared__ double sm[256];
    const int tid = threadIdx.x;
    double acc = 0.0;
    for (int k = tid; k < 2 * NPTS; k += 256)
        acc += (double)__ldcg(&g_dmin[k]);
    sm[tid] = acc;
    __syncthreads();
    for (int o = 128; o; o >>= 1) {
        if (tid < o) sm[tid] += sm[tid + o];
        __syncthreads();
    }
    if (tid == 0) out[0] = (float)(sm[0] * (1.0 / (double)NPTS));

    // re-zero bucket counts for next graph replay
    int4* gn4 = (int4*)g_n;
    const int4 z4 = make_int4(0, 0, 0, 0);
    for (int k = tid; k < 2 * NC / 4; k += 256) gn4[k] = z4;
}

extern "C" void kernel_launch(void* const* d_in, const int* in_sizes, int n_in,
                              void* d_out, int out_size) {
    const float* p_hat = (const float*)d_in[0];  // [16384,3]
    const float* p     = (const float*)d_in[1];  // [16384,3]
    float* out = (float*)d_out;

    scatter_kernel<<<32, 1024>>>(p_hat, p);
    query_kernel<<<NCTA_Q, 256>>>(p_hat, p, out);
}